// round 10
// baseline (speedup 1.0000x reference)
#include <cuda_runtime.h>
#include <math.h>

#define BATCH 1024
#define DD 128
#define G3 384
#define TT 96
#define NSTEP 95
#define S_ODE 132
#define S_GRU 388

typedef unsigned long long u64;

__device__ __align__(256) float g_traj[(size_t)TT * BATCH * DD];
__device__ __align__(256) float g_gi[(size_t)TT * BATCH * G3];
__device__ __align__(256) float g_h1[(size_t)TT * BATCH * DD];
__device__ __align__(256) float g_h2[(size_t)BATCH * DD];

// ---- packed f32x2 + fast transcendental helpers ----
__device__ __forceinline__ u64 pack2(float lo, float hi) {
    u64 r; asm("mov.b64 %0,{%1,%2};" : "=l"(r) : "f"(lo), "f"(hi)); return r;
}
__device__ __forceinline__ u64 dup2(float v) { return pack2(v, v); }
__device__ __forceinline__ void unpk2(u64 v, float& lo, float& hi) {
    asm("mov.b64 {%0,%1},%2;" : "=f"(lo), "=f"(hi) : "l"(v));
}
__device__ __forceinline__ u64 ffma2(u64 a, u64 b, u64 c) {
    u64 d; asm("fma.rn.f32x2 %0,%1,%2,%3;" : "=l"(d) : "l"(a), "l"(b), "l"(c)); return d;
}
__device__ __forceinline__ u64 fadd2(u64 a, u64 b) {
    u64 d; asm("add.rn.f32x2 %0,%1,%2;" : "=l"(d) : "l"(a), "l"(b)); return d;
}
__device__ __forceinline__ float fex2(float x) { float r; asm("ex2.approx.f32 %0,%1;" : "=f"(r) : "f"(x)); return r; }
__device__ __forceinline__ float frcp(float x) { float r; asm("rcp.approx.f32 %0,%1;" : "=f"(r) : "f"(x)); return r; }
__device__ __forceinline__ float ftanh(float x) { return 1.0f - 2.0f * frcp(fex2(2.8853900817779268f * x) + 1.0f); }
__device__ __forceinline__ float fsigm(float x) { return frcp(1.0f + fex2(-1.4426950408889634f * x)); }
__device__ __forceinline__ u64 tanh2(u64 v) {
    float a, b; unpk2(v, a, b); return pack2(ftanh(a), ftanh(b));
}

// ---------------------------------------------------------------------------
// Phase 1: Dopri5 ODE. 512 thr = 16 warps, 8 rows = 4 row-pairs (f32x2).
// Matvec role: warp (q = w>>1: k-slice of 16, ph = w&1: pairs {2ph,2ph+1}).
// Reduce/RK role: warp (p = w>>2: pair, jq = w&3: j-quarter); lane owns one j.
// ---------------------------------------------------------------------------
__global__ void __launch_bounds__(512)
ode_kernel(const float* __restrict__ yl, const float* __restrict__ yh,
           const float* __restrict__ W, const float* __restrict__ bias)
{
    extern __shared__ float sm[];
    u64* pbuf = (u64*)(sm + S_ODE * DD);   // [q(8)][pp(4)][j(128)] u64 = 32KB
    u64* xs   = pbuf + 4096;               // [pp(4)][k(128)] u64 = 4KB
    const int tid = threadIdx.x;
    for (int idx = tid; idx < DD * DD; idx += 512) {
        const int j = idx >> 7, k = idx & 127;
        sm[k * S_ODE + j] = W[idx];
    }
    const int lane = tid & 31, w = tid >> 5;
    const int q = w >> 1, ph = w & 1;      // matvec role
    const int p = w >> 2, jq = w & 3;      // reduce role
    const int j = 32 * jq + lane;
    const int rowA = blockIdx.x * 8 + 2 * p, rowB = rowA + 1;

    const u64 bv = dup2(bias[j]);

    float a0 = (j < 32) ? yl[rowA * 32 + j] : yh[rowA * 96 + j - 32];
    float b0 = (j < 32) ? yl[rowB * 32 + j] : yh[rowB * 96 + j - 32];
    u64 y = pack2(a0, b0);
    g_traj[(size_t)rowA * DD + j] = a0;
    g_traj[(size_t)rowB * DD + j] = b0;
    xs[p * 128 + j] = y;
    __syncthreads();

    const u64 dt2 = dup2(1.0f / 95.0f);
    u64 k1, k2, k3, k4, k5, k6, ar;

#define ODE_EVAL(KOUT) do { \
    u64 acc[2][4]; \
    _Pragma("unroll") \
    for (int r = 0; r < 2; r++) { acc[r][0]=0; acc[r][1]=0; acc[r][2]=0; acc[r][3]=0; } \
    _Pragma("unroll") \
    for (int kk = 0; kk < 16; kk++) { \
        const int k = 16 * q + kk; \
        const float4 wv = *(const float4*)(sm + k * S_ODE + 4 * lane); \
        const u64 w0 = dup2(wv.x), w1 = dup2(wv.y), w2 = dup2(wv.z), w3 = dup2(wv.w); \
        const u64 xA = xs[(2 * ph + 0) * 128 + k]; \
        const u64 xB = xs[(2 * ph + 1) * 128 + k]; \
        acc[0][0]=ffma2(xA,w0,acc[0][0]); acc[0][1]=ffma2(xA,w1,acc[0][1]); \
        acc[0][2]=ffma2(xA,w2,acc[0][2]); acc[0][3]=ffma2(xA,w3,acc[0][3]); \
        acc[1][0]=ffma2(xB,w0,acc[1][0]); acc[1][1]=ffma2(xB,w1,acc[1][1]); \
        acc[1][2]=ffma2(xB,w2,acc[1][2]); acc[1][3]=ffma2(xB,w3,acc[1][3]); \
    } \
    _Pragma("unroll") \
    for (int r = 0; r < 2; r++) { \
        u64* base = pbuf + (size_t)((q * 4 + 2 * ph + r)) * 128 + 4 * lane; \
        *(ulonglong2*)(base)     = make_ulonglong2(acc[r][0], acc[r][1]); \
        *(ulonglong2*)(base + 2) = make_ulonglong2(acc[r][2], acc[r][3]); \
    } \
    __syncthreads(); \
    u64 s = bv; \
    _Pragma("unroll") \
    for (int qq = 0; qq < 8; qq++) \
        s = fadd2(s, pbuf[(size_t)(qq * 4 + p) * 128 + j]); \
    KOUT = tanh2(s); \
} while (0)

#define ODE_PUSH() do { xs[p * 128 + j] = ar; __syncthreads(); } while (0)

    for (int st = 0; st < NSTEP; st++) {
        ODE_EVAL(k1);
        ar = ffma2(dup2(0.2f / 95.0f), k1, y);
        ODE_PUSH();

        ODE_EVAL(k2);
        {
            u64 s = ffma2(dup2(0.225f), k2, ffma2(dup2(0.075f), k1, (u64)0));
            ar = ffma2(dt2, s, y);
        }
        ODE_PUSH();

        ODE_EVAL(k3);
        {
            u64 s = ffma2(dup2(0.9777777777777777f), k1, (u64)0);
            s = ffma2(dup2(-3.7333333333333334f), k2, s);
            s = ffma2(dup2(3.5555555555555554f), k3, s);
            ar = ffma2(dt2, s, y);
        }
        ODE_PUSH();

        ODE_EVAL(k4);
        {
            u64 s = ffma2(dup2(2.9525906892141633f), k1, (u64)0);
            s = ffma2(dup2(-11.595793324188385f), k2, s);
            s = ffma2(dup2(9.822892851699436f), k3, s);
            s = ffma2(dup2(-0.2908093278463649f), k4, s);
            ar = ffma2(dt2, s, y);
        }
        ODE_PUSH();

        ODE_EVAL(k5);
        {
            u64 s = ffma2(dup2(2.8462752525252526f), k1, (u64)0);
            s = ffma2(dup2(-10.757575757575758f), k2, s);
            s = ffma2(dup2(8.906422717743473f), k3, s);
            s = ffma2(dup2(0.2784090909090909f), k4, s);
            s = ffma2(dup2(-0.2735313036020583f), k5, s);
            ar = ffma2(dt2, s, y);
        }
        ODE_PUSH();

        ODE_EVAL(k6);
        {
            u64 s = ffma2(dup2(0.09114583333333333f), k1, (u64)0);
            s = ffma2(dup2(0.44923629829290207f), k3, s);
            s = ffma2(dup2(0.6510416666666666f), k4, s);
            s = ffma2(dup2(-0.322376179245283f), k5, s);
            s = ffma2(dup2(0.13095238095238096f), k6, s);
            y = ffma2(dt2, s, y);
        }
        {
            float ca, cb;
            unpk2(y, ca, cb);
            g_traj[((size_t)(st + 1) * BATCH + rowA) * DD + j] = ca;
            g_traj[((size_t)(st + 1) * BATCH + rowB) * DD + j] = cb;
        }
        xs[p * 128 + j] = y;
        __syncthreads();
    }
#undef ODE_EVAL
#undef ODE_PUSH
}

// ---------------------------------------------------------------------------
// Phase 2/4: gi = X @ W_ih^T + b_ih (exact R6/R4 version). 512 thr x 4 items.
// ---------------------------------------------------------------------------
__global__ void __launch_bounds__(512)
gi_kernel(const float* __restrict__ X, const float* __restrict__ Wih,
          const float* __restrict__ bih, float* __restrict__ gi)
{
    extern __shared__ float sm[];
    const int tid = threadIdx.x;
    for (int idx = tid; idx < G3 * DD; idx += 512) {
        const int j = idx >> 7, k = idx & 127;
        sm[k * S_GRU + j] = Wih[idx];
    }
    __syncthreads();

    const int lane = tid & 31, warp = tid >> 5;
    u64 bv[3][2];
#pragma unroll
    for (int g = 0; g < 3; g++) {
        bv[g][0] = pack2(bih[128 * g + 4 * lane], bih[128 * g + 4 * lane + 1]);
        bv[g][1] = pack2(bih[128 * g + 4 * lane + 2], bih[128 * g + 4 * lane + 3]);
    }
    const float* wb = sm + 4 * lane;

#pragma unroll 1
    for (int it = 0; it < 12; it++) {
        const int item = blockIdx.x * 768 + it * 64 + warp * 4;
        float a[4][4];
#pragma unroll
        for (int i = 0; i < 4; i++) {
            const float4 v = *(const float4*)(X + (size_t)(item + i) * DD + 4 * lane);
            a[i][0] = v.x; a[i][1] = v.y; a[i][2] = v.z; a[i][3] = v.w;
        }
        u64 acc[4][3][2];
#pragma unroll
        for (int i = 0; i < 4; i++)
#pragma unroll
            for (int g = 0; g < 3; g++) { acc[i][g][0] = bv[g][0]; acc[i][g][1] = bv[g][1]; }

#pragma unroll 2
        for (int kb = 0; kb < 32; kb++) {
#pragma unroll
            for (int mk = 0; mk < 4; mk++) {
                const int k = 4 * kb + mk;
                const ulonglong2 w0 = *(const ulonglong2*)(wb + k * S_GRU);
                const ulonglong2 w1 = *(const ulonglong2*)(wb + k * S_GRU + 128);
                const ulonglong2 w2 = *(const ulonglong2*)(wb + k * S_GRU + 256);
#pragma unroll
                for (int i = 0; i < 4; i++) {
                    const u64 xd = dup2(__shfl_sync(0xffffffffu, a[i][mk], kb));
                    acc[i][0][0] = ffma2(xd, w0.x, acc[i][0][0]);
                    acc[i][0][1] = ffma2(xd, w0.y, acc[i][0][1]);
                    acc[i][1][0] = ffma2(xd, w1.x, acc[i][1][0]);
                    acc[i][1][1] = ffma2(xd, w1.y, acc[i][1][1]);
                    acc[i][2][0] = ffma2(xd, w2.x, acc[i][2][0]);
                    acc[i][2][1] = ffma2(xd, w2.y, acc[i][2][1]);
                }
            }
        }
#pragma unroll
        for (int i = 0; i < 4; i++)
#pragma unroll
            for (int g = 0; g < 3; g++)
                *(ulonglong2*)(gi + (size_t)(item + i) * G3 + 128 * g + 4 * lane) =
                    make_ulonglong2(acc[i][g][0], acc[i][g][1]);
    }
}

// ---------------------------------------------------------------------------
// Phase 3/5: GRU scan. 768 thr = 24 warps = 3 gates x 2 k-halves x 4 row-pairs.
// pbuf layout identical to R6: [(g*2+ks)*8 + row][128]. Finalize: warps 0-7.
// ---------------------------------------------------------------------------
__global__ void __launch_bounds__(768)
gru_kernel(const float* __restrict__ gi, const float* __restrict__ Whh,
           const float* __restrict__ bhh, float* __restrict__ otraj,
           float* __restrict__ olast)
{
    extern __shared__ float sm[];
    float* pbuf = sm + DD * S_GRU;   // 6144 floats
    float* xsf  = pbuf + 6144;       // 2048 floats: [row(8)][k] dup pairs
    u64* xsu = (u64*)xsf;
    const int tid = threadIdx.x;
    for (int idx = tid; idx < G3 * DD; idx += 768) {
        const int j = idx >> 7, k = idx & 127;
        sm[k * S_GRU + j] = Whh[idx];
    }
    for (int idx = tid; idx < 2048; idx += 768) xsf[idx] = 0.0f;
    __syncthreads();

    const int lane = tid & 31, wid = tid >> 5;
    // matvec role: gate g, k-half ks, row-pair rp (rows 2rp, 2rp+1)
    const int g = wid >> 3, sub = wid & 7, ks = sub >> 2, rp = sub & 3;
    const float* wb = sm + g * 128 + 4 * lane;
    float* pme = pbuf + (size_t)((g * 2 + ks) * 8 + rp * 2) * 128 + 4 * lane;
    // finalize role (warps 0..7 own one row each)
    const int frow = wid;
    const bool fin = (wid < 8);
    const int grow = blockIdx.x * 8 + frow;

    float br[4], bz[4], bn[4];
    if (fin) {
        const float4 vr = *(const float4*)(bhh + 4 * lane);
        const float4 vz = *(const float4*)(bhh + 128 + 4 * lane);
        const float4 vn = *(const float4*)(bhh + 256 + 4 * lane);
        br[0]=vr.x; br[1]=vr.y; br[2]=vr.z; br[3]=vr.w;
        bz[0]=vz.x; bz[1]=vz.y; bz[2]=vz.z; bz[3]=vz.w;
        bn[0]=vn.x; bn[1]=vn.y; bn[2]=vn.z; bn[3]=vn.w;
    }
    float h[4] = {0.f, 0.f, 0.f, 0.f};

    for (int t = 0; t < TT; t++) {
        float4 gr_, gz_, gn_;
        if (fin) {
            const float* gp = gi + ((size_t)t * BATCH + grow) * G3 + 4 * lane;
            gr_ = *(const float4*)(gp);
            gz_ = *(const float4*)(gp + 128);
            gn_ = *(const float4*)(gp + 256);
        }
        // matvec: gate g, rows {2rp, 2rp+1}, k-half ks — raw partials
        u64 acc[2][2];
        acc[0][0] = 0; acc[0][1] = 0; acc[1][0] = 0; acc[1][1] = 0;
        const int kbase = 64 * ks;
#pragma unroll 8
        for (int kk = 0; kk < 64; kk += 2) {
            const int k = kbase + kk;
            const ulonglong2 x0 = *(const ulonglong2*)(xsu + (rp * 2 + 0) * 128 + k);
            const ulonglong2 x1 = *(const ulonglong2*)(xsu + (rp * 2 + 1) * 128 + k);
            const ulonglong2 wA = *(const ulonglong2*)(wb + k * S_GRU);
            const ulonglong2 wB = *(const ulonglong2*)(wb + (k + 1) * S_GRU);
            acc[0][0] = ffma2(x0.x, wA.x, acc[0][0]); acc[0][1] = ffma2(x0.x, wA.y, acc[0][1]);
            acc[1][0] = ffma2(x1.x, wA.x, acc[1][0]); acc[1][1] = ffma2(x1.x, wA.y, acc[1][1]);
            acc[0][0] = ffma2(x0.y, wB.x, acc[0][0]); acc[0][1] = ffma2(x0.y, wB.y, acc[0][1]);
            acc[1][0] = ffma2(x1.y, wB.x, acc[1][0]); acc[1][1] = ffma2(x1.y, wB.y, acc[1][1]);
        }
        *(ulonglong2*)(pme)       = make_ulonglong2(acc[0][0], acc[0][1]);
        *(ulonglong2*)(pme + 128) = make_ulonglong2(acc[1][0], acc[1][1]);
        __syncthreads();   // A: all partials visible

        if (fin) {
            const float* pb = pbuf + (size_t)frow * 128 + 4 * lane;
            const ulonglong2 pr0 = *(const ulonglong2*)(pb);
            const ulonglong2 pr1 = *(const ulonglong2*)(pb + 8 * 128);
            const ulonglong2 pz0 = *(const ulonglong2*)(pb + 16 * 128);
            const ulonglong2 pz1 = *(const ulonglong2*)(pb + 24 * 128);
            const ulonglong2 pn0 = *(const ulonglong2*)(pb + 32 * 128);
            const ulonglong2 pn1 = *(const ulonglong2*)(pb + 40 * 128);
            float ar[4], az[4], an[4];
            {
                const u64 s0 = fadd2(pr0.x, pr1.x), s1 = fadd2(pr0.y, pr1.y);
                unpk2(s0, ar[0], ar[1]); unpk2(s1, ar[2], ar[3]);
            }
            {
                const u64 s0 = fadd2(pz0.x, pz1.x), s1 = fadd2(pz0.y, pz1.y);
                unpk2(s0, az[0], az[1]); unpk2(s1, az[2], az[3]);
            }
            {
                const u64 s0 = fadd2(pn0.x, pn1.x), s1 = fadd2(pn0.y, pn1.y);
                unpk2(s0, an[0], an[1]); unpk2(s1, an[2], an[3]);
            }
            const float gvr[4] = {gr_.x, gr_.y, gr_.z, gr_.w};
            const float gvz[4] = {gz_.x, gz_.y, gz_.z, gz_.w};
            const float gvn[4] = {gn_.x, gn_.y, gn_.z, gn_.w};
#pragma unroll
            for (int m = 0; m < 4; m++) {
                const float rg = fsigm(gvr[m] + ar[m] + br[m]);
                const float zg = fsigm(gvz[m] + az[m] + bz[m]);
                const float ng = ftanh(gvn[m] + rg * (an[m] + bn[m]));
                h[m] = ng + zg * (h[m] - ng);
            }
            float* xme = xsf + (size_t)(frow * 128 + 4 * lane) * 2;
            *(float4*)(xme)     = make_float4(h[0], h[0], h[1], h[1]);
            *(float4*)(xme + 4) = make_float4(h[2], h[2], h[3], h[3]);
            if (otraj)
                *(float4*)(otraj + ((size_t)t * BATCH + grow) * DD + 4 * lane) =
                    make_float4(h[0], h[1], h[2], h[3]);
        }
        __syncthreads();   // B: new h visible
    }
    if (olast && fin)
        *(float4*)(olast + (size_t)grow * DD + 4 * lane) =
            make_float4(h[0], h[1], h[2], h[3]);
}

// ---------------------------------------------------------------------------
// Phase 6: FC head (unchanged).
// ---------------------------------------------------------------------------
__global__ void __launch_bounds__(256)
fc_kernel(const float* __restrict__ W1, const float* __restrict__ b1,
          const float* __restrict__ W2, const float* __restrict__ b2,
          float* __restrict__ out)
{
    extern __shared__ float sm[];
    float* hs = sm;
    float* hd = sm + 1024;
    float* wt = sm + 1536;
    const int tid = threadIdx.x;
    const int row0 = blockIdx.x * 8;

    for (int idx = tid; idx < 8 * DD; idx += 256) hs[idx] = g_h2[(size_t)row0 * DD + idx];
    for (int idx = tid; idx < 64 * DD; idx += 256) {
        const int j = idx >> 7, k = idx & 127;
        wt[k * 68 + j] = W1[idx];
    }
    __syncthreads();

#pragma unroll
    for (int i = 0; i < 2; i++) {
        const int p = tid + 256 * i, r = p >> 6, j = p & 63;
        float acc = b1[j];
#pragma unroll 8
        for (int k = 0; k < DD; k++) acc = fmaf(hs[r * DD + k], wt[k * 68 + j], acc);
        hd[r * 64 + j] = acc * normcdff(acc);
    }

    for (int c = 0; c < 12; c++) {
        __syncthreads();
        for (int idx = tid; idx < 256 * 64; idx += 256) {
            const int jj = idx >> 6, k = idx & 63;
            wt[k * 260 + jj] = W2[(size_t)(c * 256 + jj) * 64 + k];
        }
        __syncthreads();
        const int j = c * 256 + tid;
        float acc[8];
#pragma unroll
        for (int r = 0; r < 8; r++) acc[r] = b2[j];
#pragma unroll 8
        for (int k = 0; k < 64; k++) {
            const float w = wt[k * 260 + tid];
#pragma unroll
            for (int r = 0; r < 8; r++) acc[r] = fmaf(hd[r * 64 + k], w, acc[r]);
        }
#pragma unroll
        for (int r = 0; r < 8; r++) out[(size_t)(row0 + r) * 3072 + j] = acc[r];
    }
}

// ---------------------------------------------------------------------------
extern "C" void kernel_launch(void* const* d_in, const int* in_sizes, int n_in,
                              void* d_out, int out_size)
{
    (void)in_sizes; (void)n_in; (void)out_size;
    const float* yl    = (const float*)d_in[1];
    const float* yh    = (const float*)d_in[2];
    const float* W_ode = (const float*)d_in[3];
    const float* b_ode = (const float*)d_in[4];
    const float* W_ih0 = (const float*)d_in[5];
    const float* W_hh0 = (const float*)d_in[6];
    const float* b_ih0 = (const float*)d_in[7];
    const float* b_hh0 = (const float*)d_in[8];
    const float* W_ih1 = (const float*)d_in[9];
    const float* W_hh1 = (const float*)d_in[10];
    const float* b_ih1 = (const float*)d_in[11];
    const float* b_hh1 = (const float*)d_in[12];
    const float* W1    = (const float*)d_in[13];
    const float* b1    = (const float*)d_in[14];
    const float* W2    = (const float*)d_in[15];
    const float* b2    = (const float*)d_in[16];
    float* out = (float*)d_out;

    float *traj, *gibuf, *h1, *h2;
    cudaGetSymbolAddress((void**)&traj,  g_traj);
    cudaGetSymbolAddress((void**)&gibuf, g_gi);
    cudaGetSymbolAddress((void**)&h1,    g_h1);
    cudaGetSymbolAddress((void**)&h2,    g_h2);

    const int SM_ODE  = S_ODE * DD * 4 + 32768 + 4096;    // 104,448 B
    const int SM_GI   = S_GRU * DD * 4;                   // 198,656 B
    const int SM_GRU2 = (S_GRU * DD + 6144 + 2048) * 4;   // 231,424 B
    const int SM_FC   = (1536 + 64 * 260) * 4;            //  72,704 B
    cudaFuncSetAttribute(ode_kernel, cudaFuncAttributeMaxDynamicSharedMemorySize, SM_ODE);
    cudaFuncSetAttribute(gi_kernel,  cudaFuncAttributeMaxDynamicSharedMemorySize, SM_GI);
    cudaFuncSetAttribute(gru_kernel, cudaFuncAttributeMaxDynamicSharedMemorySize, SM_GRU2);
    cudaFuncSetAttribute(fc_kernel,  cudaFuncAttributeMaxDynamicSharedMemorySize, SM_FC);

    ode_kernel<<<128, 512, SM_ODE>>>(yl, yh, W_ode, b_ode);
    gi_kernel <<<128, 512, SM_GI>>>(traj, W_ih0, b_ih0, gibuf);
    gru_kernel<<<128, 768, SM_GRU2>>>(gibuf, W_hh0, b_hh0, h1, nullptr);
    gi_kernel <<<128, 512, SM_GI>>>(h1, W_ih1, b_ih1, gibuf);
    gru_kernel<<<128, 768, SM_GRU2>>>(gibuf, W_hh1, b_hh1, nullptr, h2);
    fc_kernel <<<128, 256, SM_FC>>>(W1, b1, W2, b2, out);
}

// round 11
// speedup vs baseline: 1.1488x; 1.1488x over previous
#include <cuda_runtime.h>
#include <math.h>

#define BATCH 1024
#define DD 128
#define G3 384
#define TT 96
#define NSTEP 95
#define S_ODE 132
#define S_GRU 388

typedef unsigned long long u64;

__device__ __align__(256) float g_traj[(size_t)TT * BATCH * DD];
__device__ __align__(256) float g_gi[(size_t)TT * BATCH * G3];
__device__ __align__(256) float g_h1[(size_t)TT * BATCH * DD];
__device__ __align__(256) float g_h2[(size_t)BATCH * DD];

// ---- packed f32x2 + fast transcendental helpers ----
__device__ __forceinline__ u64 pack2(float lo, float hi) {
    u64 r; asm("mov.b64 %0,{%1,%2};" : "=l"(r) : "f"(lo), "f"(hi)); return r;
}
__device__ __forceinline__ u64 dup2(float v) { return pack2(v, v); }
__device__ __forceinline__ void unpk2(u64 v, float& lo, float& hi) {
    asm("mov.b64 {%0,%1},%2;" : "=f"(lo), "=f"(hi) : "l"(v));
}
__device__ __forceinline__ u64 ffma2(u64 a, u64 b, u64 c) {
    u64 d; asm("fma.rn.f32x2 %0,%1,%2,%3;" : "=l"(d) : "l"(a), "l"(b), "l"(c)); return d;
}
__device__ __forceinline__ u64 fadd2(u64 a, u64 b) {
    u64 d; asm("add.rn.f32x2 %0,%1,%2;" : "=l"(d) : "l"(a), "l"(b)); return d;
}
__device__ __forceinline__ float fex2(float x) { float r; asm("ex2.approx.f32 %0,%1;" : "=f"(r) : "f"(x)); return r; }
__device__ __forceinline__ float frcp(float x) { float r; asm("rcp.approx.f32 %0,%1;" : "=f"(r) : "f"(x)); return r; }
__device__ __forceinline__ float ftanh(float x) { return 1.0f - 2.0f * frcp(fex2(2.8853900817779268f * x) + 1.0f); }
__device__ __forceinline__ float fsigm(float x) { return frcp(1.0f + fex2(-1.4426950408889634f * x)); }
__device__ __forceinline__ u64 tanh2(u64 v) {
    float a, b; unpk2(v, a, b); return pack2(ftanh(a), ftanh(b));
}

// ---------------------------------------------------------------------------
// Phase 1: Dopri5 ODE. 4 rows (2 f32x2 pairs) per CTA, 256 thr = 8 warps,
// 256 CTAs -> 2 CTAs/SM (independent barrier domains).
// Matvec role: warp q does k-slice [16q,16q+16) for both pairs.
// Reduce/RK role: warp (p = w>>2: pair, jq = w&3); lane owns j = 32*jq+lane.
// ---------------------------------------------------------------------------
__global__ void __launch_bounds__(256, 2)
ode_kernel(const float* __restrict__ yl, const float* __restrict__ yh,
           const float* __restrict__ W, const float* __restrict__ bias)
{
    extern __shared__ float sm[];
    u64* pbuf = (u64*)(sm + S_ODE * DD);   // [q(8)][pp(2)][j(128)] u64 = 16KB
    u64* xs   = pbuf + 2048;               // [pp(2)][k(128)] u64 = 2KB
    const int tid = threadIdx.x;
    for (int idx = tid; idx < DD * DD; idx += 256) {
        const int j = idx >> 7, k = idx & 127;
        sm[k * S_ODE + j] = W[idx];
    }
    const int lane = tid & 31, w = tid >> 5;
    const int q = w;                       // matvec k-slice
    const int p = w >> 2, jq = w & 3;      // reduce role
    const int j = 32 * jq + lane;
    const int rowA = blockIdx.x * 4 + 2 * p, rowB = rowA + 1;

    const u64 bv = dup2(bias[j]);

    float a0 = (j < 32) ? yl[rowA * 32 + j] : yh[rowA * 96 + j - 32];
    float b0 = (j < 32) ? yl[rowB * 32 + j] : yh[rowB * 96 + j - 32];
    u64 y = pack2(a0, b0);
    g_traj[(size_t)rowA * DD + j] = a0;
    g_traj[(size_t)rowB * DD + j] = b0;
    xs[p * 128 + j] = y;
    __syncthreads();

    const u64 dt2 = dup2(1.0f / 95.0f);
    u64 k1, k2, k3, k4, k5, k6, ar;

#define ODE_EVAL(KOUT) do { \
    u64 acc[2][4]; \
    acc[0][0]=0; acc[0][1]=0; acc[0][2]=0; acc[0][3]=0; \
    acc[1][0]=0; acc[1][1]=0; acc[1][2]=0; acc[1][3]=0; \
    _Pragma("unroll") \
    for (int kk = 0; kk < 16; kk++) { \
        const int k = 16 * q + kk; \
        const float4 wv = *(const float4*)(sm + k * S_ODE + 4 * lane); \
        const u64 w0 = dup2(wv.x), w1 = dup2(wv.y), w2 = dup2(wv.z), w3 = dup2(wv.w); \
        const u64 xA = xs[k], xB = xs[128 + k]; \
        acc[0][0]=ffma2(xA,w0,acc[0][0]); acc[0][1]=ffma2(xA,w1,acc[0][1]); \
        acc[0][2]=ffma2(xA,w2,acc[0][2]); acc[0][3]=ffma2(xA,w3,acc[0][3]); \
        acc[1][0]=ffma2(xB,w0,acc[1][0]); acc[1][1]=ffma2(xB,w1,acc[1][1]); \
        acc[1][2]=ffma2(xB,w2,acc[1][2]); acc[1][3]=ffma2(xB,w3,acc[1][3]); \
    } \
    _Pragma("unroll") \
    for (int pp = 0; pp < 2; pp++) { \
        u64* base = pbuf + (size_t)(q * 2 + pp) * 128 + 4 * lane; \
        *(ulonglong2*)(base)     = make_ulonglong2(acc[pp][0], acc[pp][1]); \
        *(ulonglong2*)(base + 2) = make_ulonglong2(acc[pp][2], acc[pp][3]); \
    } \
    __syncthreads(); \
    u64 s = bv; \
    _Pragma("unroll") \
    for (int qq = 0; qq < 8; qq++) \
        s = fadd2(s, pbuf[(size_t)(qq * 2 + p) * 128 + j]); \
    KOUT = tanh2(s); \
} while (0)

#define ODE_PUSH() do { xs[p * 128 + j] = ar; __syncthreads(); } while (0)

    for (int st = 0; st < NSTEP; st++) {
        ODE_EVAL(k1);
        ar = ffma2(dup2(0.2f / 95.0f), k1, y);
        ODE_PUSH();

        ODE_EVAL(k2);
        {
            u64 s = ffma2(dup2(0.225f), k2, ffma2(dup2(0.075f), k1, (u64)0));
            ar = ffma2(dt2, s, y);
        }
        ODE_PUSH();

        ODE_EVAL(k3);
        {
            u64 s = ffma2(dup2(0.9777777777777777f), k1, (u64)0);
            s = ffma2(dup2(-3.7333333333333334f), k2, s);
            s = ffma2(dup2(3.5555555555555554f), k3, s);
            ar = ffma2(dt2, s, y);
        }
        ODE_PUSH();

        ODE_EVAL(k4);
        {
            u64 s = ffma2(dup2(2.9525906892141633f), k1, (u64)0);
            s = ffma2(dup2(-11.595793324188385f), k2, s);
            s = ffma2(dup2(9.822892851699436f), k3, s);
            s = ffma2(dup2(-0.2908093278463649f), k4, s);
            ar = ffma2(dt2, s, y);
        }
        ODE_PUSH();

        ODE_EVAL(k5);
        {
            u64 s = ffma2(dup2(2.8462752525252526f), k1, (u64)0);
            s = ffma2(dup2(-10.757575757575758f), k2, s);
            s = ffma2(dup2(8.906422717743473f), k3, s);
            s = ffma2(dup2(0.2784090909090909f), k4, s);
            s = ffma2(dup2(-0.2735313036020583f), k5, s);
            ar = ffma2(dt2, s, y);
        }
        ODE_PUSH();

        ODE_EVAL(k6);
        {
            u64 s = ffma2(dup2(0.09114583333333333f), k1, (u64)0);
            s = ffma2(dup2(0.44923629829290207f), k3, s);
            s = ffma2(dup2(0.6510416666666666f), k4, s);
            s = ffma2(dup2(-0.322376179245283f), k5, s);
            s = ffma2(dup2(0.13095238095238096f), k6, s);
            y = ffma2(dt2, s, y);
        }
        {
            float ca, cb;
            unpk2(y, ca, cb);
            g_traj[((size_t)(st + 1) * BATCH + rowA) * DD + j] = ca;
            g_traj[((size_t)(st + 1) * BATCH + rowB) * DD + j] = cb;
        }
        xs[p * 128 + j] = y;
        __syncthreads();
    }
#undef ODE_EVAL
#undef ODE_PUSH
}

// ---------------------------------------------------------------------------
// Phase 2/4: gi = X @ W_ih^T + b_ih (exact R6/R4 version). 512 thr x 4 items.
// ---------------------------------------------------------------------------
__global__ void __launch_bounds__(512)
gi_kernel(const float* __restrict__ X, const float* __restrict__ Wih,
          const float* __restrict__ bih, float* __restrict__ gi)
{
    extern __shared__ float sm[];
    const int tid = threadIdx.x;
    for (int idx = tid; idx < G3 * DD; idx += 512) {
        const int j = idx >> 7, k = idx & 127;
        sm[k * S_GRU + j] = Wih[idx];
    }
    __syncthreads();

    const int lane = tid & 31, warp = tid >> 5;
    u64 bv[3][2];
#pragma unroll
    for (int g = 0; g < 3; g++) {
        bv[g][0] = pack2(bih[128 * g + 4 * lane], bih[128 * g + 4 * lane + 1]);
        bv[g][1] = pack2(bih[128 * g + 4 * lane + 2], bih[128 * g + 4 * lane + 3]);
    }
    const float* wb = sm + 4 * lane;

#pragma unroll 1
    for (int it = 0; it < 12; it++) {
        const int item = blockIdx.x * 768 + it * 64 + warp * 4;
        float a[4][4];
#pragma unroll
        for (int i = 0; i < 4; i++) {
            const float4 v = *(const float4*)(X + (size_t)(item + i) * DD + 4 * lane);
            a[i][0] = v.x; a[i][1] = v.y; a[i][2] = v.z; a[i][3] = v.w;
        }
        u64 acc[4][3][2];
#pragma unroll
        for (int i = 0; i < 4; i++)
#pragma unroll
            for (int g = 0; g < 3; g++) { acc[i][g][0] = bv[g][0]; acc[i][g][1] = bv[g][1]; }

#pragma unroll 2
        for (int kb = 0; kb < 32; kb++) {
#pragma unroll
            for (int mk = 0; mk < 4; mk++) {
                const int k = 4 * kb + mk;
                const ulonglong2 w0 = *(const ulonglong2*)(wb + k * S_GRU);
                const ulonglong2 w1 = *(const ulonglong2*)(wb + k * S_GRU + 128);
                const ulonglong2 w2 = *(const ulonglong2*)(wb + k * S_GRU + 256);
#pragma unroll
                for (int i = 0; i < 4; i++) {
                    const u64 xd = dup2(__shfl_sync(0xffffffffu, a[i][mk], kb));
                    acc[i][0][0] = ffma2(xd, w0.x, acc[i][0][0]);
                    acc[i][0][1] = ffma2(xd, w0.y, acc[i][0][1]);
                    acc[i][1][0] = ffma2(xd, w1.x, acc[i][1][0]);
                    acc[i][1][1] = ffma2(xd, w1.y, acc[i][1][1]);
                    acc[i][2][0] = ffma2(xd, w2.x, acc[i][2][0]);
                    acc[i][2][1] = ffma2(xd, w2.y, acc[i][2][1]);
                }
            }
        }
#pragma unroll
        for (int i = 0; i < 4; i++)
#pragma unroll
            for (int g = 0; g < 3; g++)
                *(ulonglong2*)(gi + (size_t)(item + i) * G3 + 128 * g + 4 * lane) =
                    make_ulonglong2(acc[i][g][0], acc[i][g][1]);
    }
}

// ---------------------------------------------------------------------------
// Phase 3/5: GRU scan (exact R6 version). 384 thr, 2 barriers/t.
// ---------------------------------------------------------------------------
__global__ void __launch_bounds__(384)
gru_kernel(const float* __restrict__ gi, const float* __restrict__ Whh,
           const float* __restrict__ bhh, float* __restrict__ otraj,
           float* __restrict__ olast)
{
    extern __shared__ float sm[];
    float* pbuf = sm + DD * S_GRU;   // 6144 floats: [(g*2+ks)*8 + row][128]
    float* xsf  = pbuf + 6144;       // 2048 floats: [row(8)][k] dup pairs
    u64* xsu = (u64*)xsf;
    const int tid = threadIdx.x;
    for (int idx = tid; idx < G3 * DD; idx += 384) {
        const int j = idx >> 7, k = idx & 127;
        sm[k * S_GRU + j] = Whh[idx];
    }
    for (int idx = tid; idx < 2048; idx += 384) xsf[idx] = 0.0f;
    __syncthreads();

    const int lane = tid & 31, wid = tid >> 5;
    const int g = wid >> 2, ks = (wid >> 1) & 1, rh = wid & 1;
    const float* wb = sm + g * 128 + 4 * lane;
    float* pme = pbuf + (size_t)((g * 2 + ks) * 8 + rh * 4) * 128 + 4 * lane;
    const int frow = wid;
    const bool fin = (wid < 8);
    const int grow = blockIdx.x * 8 + frow;

    float br[4], bz[4], bn[4];
    if (fin) {
        const float4 vr = *(const float4*)(bhh + 4 * lane);
        const float4 vz = *(const float4*)(bhh + 128 + 4 * lane);
        const float4 vn = *(const float4*)(bhh + 256 + 4 * lane);
        br[0]=vr.x; br[1]=vr.y; br[2]=vr.z; br[3]=vr.w;
        bz[0]=vz.x; bz[1]=vz.y; bz[2]=vz.z; bz[3]=vz.w;
        bn[0]=vn.x; bn[1]=vn.y; bn[2]=vn.z; bn[3]=vn.w;
    }
    float h[4] = {0.f, 0.f, 0.f, 0.f};

    for (int t = 0; t < TT; t++) {
        float4 gr_, gz_, gn_;
        if (fin) {
            const float* gp = gi + ((size_t)t * BATCH + grow) * G3 + 4 * lane;
            gr_ = *(const float4*)(gp);
            gz_ = *(const float4*)(gp + 128);
            gn_ = *(const float4*)(gp + 256);
        }
        u64 acc[4][2];
#pragma unroll
        for (int r = 0; r < 4; r++) { acc[r][0] = 0; acc[r][1] = 0; }
        const int kbase = 64 * ks;
#pragma unroll 8
        for (int kk = 0; kk < 64; kk += 2) {
            const int k = kbase + kk;
            const ulonglong2 x0 = *(const ulonglong2*)(xsu + (rh * 4 + 0) * 128 + k);
            const ulonglong2 x1 = *(const ulonglong2*)(xsu + (rh * 4 + 1) * 128 + k);
            const ulonglong2 x2 = *(const ulonglong2*)(xsu + (rh * 4 + 2) * 128 + k);
            const ulonglong2 x3 = *(const ulonglong2*)(xsu + (rh * 4 + 3) * 128 + k);
            const ulonglong2 wA = *(const ulonglong2*)(wb + k * S_GRU);
            const ulonglong2 wB = *(const ulonglong2*)(wb + (k + 1) * S_GRU);
            acc[0][0] = ffma2(x0.x, wA.x, acc[0][0]); acc[0][1] = ffma2(x0.x, wA.y, acc[0][1]);
            acc[1][0] = ffma2(x1.x, wA.x, acc[1][0]); acc[1][1] = ffma2(x1.x, wA.y, acc[1][1]);
            acc[2][0] = ffma2(x2.x, wA.x, acc[2][0]); acc[2][1] = ffma2(x2.x, wA.y, acc[2][1]);
            acc[3][0] = ffma2(x3.x, wA.x, acc[3][0]); acc[3][1] = ffma2(x3.x, wA.y, acc[3][1]);
            acc[0][0] = ffma2(x0.y, wB.x, acc[0][0]); acc[0][1] = ffma2(x0.y, wB.y, acc[0][1]);
            acc[1][0] = ffma2(x1.y, wB.x, acc[1][0]); acc[1][1] = ffma2(x1.y, wB.y, acc[1][1]);
            acc[2][0] = ffma2(x2.y, wB.x, acc[2][0]); acc[2][1] = ffma2(x2.y, wB.y, acc[2][1]);
            acc[3][0] = ffma2(x3.y, wB.x, acc[3][0]); acc[3][1] = ffma2(x3.y, wB.y, acc[3][1]);
        }
#pragma unroll
        for (int r = 0; r < 4; r++)
            *(ulonglong2*)(pme + r * 128) = make_ulonglong2(acc[r][0], acc[r][1]);
        __syncthreads();   // A: all partials visible

        if (fin) {
            const float* pb = pbuf + (size_t)frow * 128 + 4 * lane;
            const ulonglong2 pr0 = *(const ulonglong2*)(pb);
            const ulonglong2 pr1 = *(const ulonglong2*)(pb + 8 * 128);
            const ulonglong2 pz0 = *(const ulonglong2*)(pb + 16 * 128);
            const ulonglong2 pz1 = *(const ulonglong2*)(pb + 24 * 128);
            const ulonglong2 pn0 = *(const ulonglong2*)(pb + 32 * 128);
            const ulonglong2 pn1 = *(const ulonglong2*)(pb + 40 * 128);
            float ar[4], az[4], an[4];
            {
                const u64 s0 = fadd2(pr0.x, pr1.x), s1 = fadd2(pr0.y, pr1.y);
                unpk2(s0, ar[0], ar[1]); unpk2(s1, ar[2], ar[3]);
            }
            {
                const u64 s0 = fadd2(pz0.x, pz1.x), s1 = fadd2(pz0.y, pz1.y);
                unpk2(s0, az[0], az[1]); unpk2(s1, az[2], az[3]);
            }
            {
                const u64 s0 = fadd2(pn0.x, pn1.x), s1 = fadd2(pn0.y, pn1.y);
                unpk2(s0, an[0], an[1]); unpk2(s1, an[2], an[3]);
            }
            const float gvr[4] = {gr_.x, gr_.y, gr_.z, gr_.w};
            const float gvz[4] = {gz_.x, gz_.y, gz_.z, gz_.w};
            const float gvn[4] = {gn_.x, gn_.y, gn_.z, gn_.w};
#pragma unroll
            for (int m = 0; m < 4; m++) {
                const float rg = fsigm(gvr[m] + ar[m] + br[m]);
                const float zg = fsigm(gvz[m] + az[m] + bz[m]);
                const float ng = ftanh(gvn[m] + rg * (an[m] + bn[m]));
                h[m] = ng + zg * (h[m] - ng);
            }
            float* xme = xsf + (size_t)(frow * 128 + 4 * lane) * 2;
            *(float4*)(xme)     = make_float4(h[0], h[0], h[1], h[1]);
            *(float4*)(xme + 4) = make_float4(h[2], h[2], h[3], h[3]);
            if (otraj)
                *(float4*)(otraj + ((size_t)t * BATCH + grow) * DD + 4 * lane) =
                    make_float4(h[0], h[1], h[2], h[3]);
        }
        __syncthreads();   // C: new h visible
    }
    if (olast && fin)
        *(float4*)(olast + (size_t)grow * DD + 4 * lane) =
            make_float4(h[0], h[1], h[2], h[3]);
}

// ---------------------------------------------------------------------------
// Phase 6: FC head (unchanged).
// ---------------------------------------------------------------------------
__global__ void __launch_bounds__(256)
fc_kernel(const float* __restrict__ W1, const float* __restrict__ b1,
          const float* __restrict__ W2, const float* __restrict__ b2,
          float* __restrict__ out)
{
    extern __shared__ float sm[];
    float* hs = sm;
    float* hd = sm + 1024;
    float* wt = sm + 1536;
    const int tid = threadIdx.x;
    const int row0 = blockIdx.x * 8;

    for (int idx = tid; idx < 8 * DD; idx += 256) hs[idx] = g_h2[(size_t)row0 * DD + idx];
    for (int idx = tid; idx < 64 * DD; idx += 256) {
        const int j = idx >> 7, k = idx & 127;
        wt[k * 68 + j] = W1[idx];
    }
    __syncthreads();

#pragma unroll
    for (int i = 0; i < 2; i++) {
        const int p = tid + 256 * i, r = p >> 6, j = p & 63;
        float acc = b1[j];
#pragma unroll 8
        for (int k = 0; k < DD; k++) acc = fmaf(hs[r * DD + k], wt[k * 68 + j], acc);
        hd[r * 64 + j] = acc * normcdff(acc);
    }

    for (int c = 0; c < 12; c++) {
        __syncthreads();
        for (int idx = tid; idx < 256 * 64; idx += 256) {
            const int jj = idx >> 6, k = idx & 63;
            wt[k * 260 + jj] = W2[(size_t)(c * 256 + jj) * 64 + k];
        }
        __syncthreads();
        const int j = c * 256 + tid;
        float acc[8];
#pragma unroll
        for (int r = 0; r < 8; r++) acc[r] = b2[j];
#pragma unroll 8
        for (int k = 0; k < 64; k++) {
            const float w = wt[k * 260 + tid];
#pragma unroll
            for (int r = 0; r < 8; r++) acc[r] = fmaf(hd[r * 64 + k], w, acc[r]);
        }
#pragma unroll
        for (int r = 0; r < 8; r++) out[(size_t)(row0 + r) * 3072 + j] = acc[r];
    }
}

// ---------------------------------------------------------------------------
extern "C" void kernel_launch(void* const* d_in, const int* in_sizes, int n_in,
                              void* d_out, int out_size)
{
    (void)in_sizes; (void)n_in; (void)out_size;
    const float* yl    = (const float*)d_in[1];
    const float* yh    = (const float*)d_in[2];
    const float* W_ode = (const float*)d_in[3];
    const float* b_ode = (const float*)d_in[4];
    const float* W_ih0 = (const float*)d_in[5];
    const float* W_hh0 = (const float*)d_in[6];
    const float* b_ih0 = (const float*)d_in[7];
    const float* b_hh0 = (const float*)d_in[8];
    const float* W_ih1 = (const float*)d_in[9];
    const float* W_hh1 = (const float*)d_in[10];
    const float* b_ih1 = (const float*)d_in[11];
    const float* b_hh1 = (const float*)d_in[12];
    const float* W1    = (const float*)d_in[13];
    const float* b1    = (const float*)d_in[14];
    const float* W2    = (const float*)d_in[15];
    const float* b2    = (const float*)d_in[16];
    float* out = (float*)d_out;

    float *traj, *gibuf, *h1, *h2;
    cudaGetSymbolAddress((void**)&traj,  g_traj);
    cudaGetSymbolAddress((void**)&gibuf, g_gi);
    cudaGetSymbolAddress((void**)&h1,    g_h1);
    cudaGetSymbolAddress((void**)&h2,    g_h2);

    const int SM_ODE  = S_ODE * DD * 4 + 16384 + 2048;    //  86,016 B (x2/SM)
    const int SM_GI   = S_GRU * DD * 4;                   // 198,656 B
    const int SM_GRU2 = (S_GRU * DD + 6144 + 2048) * 4;   // 231,424 B
    const int SM_FC   = (1536 + 64 * 260) * 4;            //  72,704 B
    cudaFuncSetAttribute(ode_kernel, cudaFuncAttributeMaxDynamicSharedMemorySize, SM_ODE);
    cudaFuncSetAttribute(gi_kernel,  cudaFuncAttributeMaxDynamicSharedMemorySize, SM_GI);
    cudaFuncSetAttribute(gru_kernel, cudaFuncAttributeMaxDynamicSharedMemorySize, SM_GRU2);
    cudaFuncSetAttribute(fc_kernel,  cudaFuncAttributeMaxDynamicSharedMemorySize, SM_FC);

    ode_kernel<<<256, 256, SM_ODE>>>(yl, yh, W_ode, b_ode);
    gi_kernel <<<128, 512, SM_GI>>>(traj, W_ih0, b_ih0, gibuf);
    gru_kernel<<<128, 384, SM_GRU2>>>(gibuf, W_hh0, b_hh0, h1, nullptr);
    gi_kernel <<<128, 512, SM_GI>>>(h1, W_ih1, b_ih1, gibuf);
    gru_kernel<<<128, 384, SM_GRU2>>>(gibuf, W_hh1, b_hh1, nullptr, h2);
    fc_kernel <<<128, 256, SM_FC>>>(W1, b1, W2, b2, out);
}